// round 6
// baseline (speedup 1.0000x reference)
#include <cuda_runtime.h>
#include <cstdint>
#include <cstdlib>

#define BATCH   8
#define NSEQ    1024
#define EMB     768
#define NHEADS  12
#define HDIM    64
#define MTOT    (BATCH * NSEQ)

__device__ float g_s[3 * NHEADS * NSEQ * HDIM];   // 9 MiB scratch: one batch of Q,K,V

namespace {
struct EagerLoad { EagerLoad() { setenv("CUDA_MODULE_LOADING", "EAGER", 1); } };
EagerLoad eager_load_instance_;
}

// ---------------------------------------------------------------------------
// tf32 helpers. Split x = hi + lo with hi = rna_tf32(x), lo = rna_tf32(x-hi).
// tf32x3 mma: D += hi_a*hi_b + hi_a*lo_b + lo_a*hi_b  (error ~ eps^2).
// ---------------------------------------------------------------------------
__device__ __forceinline__ unsigned f2tf(float x) {
    unsigned r;
    asm("cvt.rna.tf32.f32 %0, %1;" : "=r"(r) : "f"(x));
    return r;
}
__device__ __forceinline__ float f2tff(float x) { return __uint_as_float(f2tf(x)); }

__device__ __forceinline__ void mma8(float* c, const unsigned* a, const unsigned* b) {
    asm volatile(
        "mma.sync.aligned.m16n8k8.row.col.f32.tf32.tf32.f32 "
        "{%0,%1,%2,%3}, {%4,%5,%6,%7}, {%8,%9}, {%0,%1,%2,%3};\n"
        : "+f"(c[0]), "+f"(c[1]), "+f"(c[2]), "+f"(c[3])
        : "r"(a[0]), "r"(a[1]), "r"(a[2]), "r"(a[3]), "r"(b[0]), "r"(b[1]));
}

__device__ __forceinline__ float4 hi4(float4 v) {
    return make_float4(f2tff(v.x), f2tff(v.y), f2tff(v.z), f2tff(v.w));
}
__device__ __forceinline__ float4 lo4(float4 v, float4 h) {
    return make_float4(f2tff(v.x - h.x), f2tff(v.y - h.y),
                       f2tff(v.z - h.z), f2tff(v.w - h.w));
}

// ---------------------------------------------------------------------------
// Fused QKV GEMM (tf32x3) for one batch: [1024 x 2304], 128x128 tiles,
// grid (18,8). Single-buffered hi/lo smem + register prefetch.
// ---------------------------------------------------------------------------
#define GEMM_SMEM (4 * 128 * 36 * 4)   // Ah, Al, Bh, Bl

__global__ __launch_bounds__(256) void qkv_gemm_kernel(
    const float* __restrict__ x,
    const float* __restrict__ wq, const float* __restrict__ bq,
    const float* __restrict__ wk, const float* __restrict__ bk,
    const float* __restrict__ wv, const float* __restrict__ bv,
    int group)
{
    extern __shared__ float sm[];
    float* Ah = sm;
    float* Al = sm + 128 * 36;
    float* Bh = sm + 2 * 128 * 36;
    float* Bl = sm + 3 * 128 * 36;

    const int bx = blockIdx.x;
    const int by = blockIdx.y;
    const int sel = bx / 6;
    const int bxx = bx % 6;
    const float* W    = (sel == 0) ? wq : (sel == 1) ? wk : wv;
    const float* bias = (sel == 0) ? bq : (sel == 1) ? bk : bv;
    const float* A = x + (size_t)group * NSEQ * EMB;

    const int tid = threadIdx.x;
    const int lane = tid & 31;
    const int w = tid >> 5;
    const int wm = w & 3;
    const int wn = w >> 2;
    const int gid = lane >> 2;
    const int tig = lane & 3;

    const int lrow = tid >> 1;
    const int lcol = (tid & 1) * 16;

    const float* Ag = A + (size_t)(by * 128 + lrow) * EMB + lcol;
    const float* Wg = W + (size_t)(bxx * 128 + lrow) * EMB + lcol;

    float acc[2][8][4];
#pragma unroll
    for (int mt = 0; mt < 2; mt++)
#pragma unroll
        for (int nt = 0; nt < 8; nt++)
#pragma unroll
            for (int i = 0; i < 4; i++) acc[mt][nt][i] = 0.f;

    float4 ra[4], rb[4];
#pragma unroll
    for (int j = 0; j < 4; j++) {
        ra[j] = *(const float4*)(Ag + j * 4);
        rb[j] = *(const float4*)(Wg + j * 4);
    }

    const int NKT = EMB / 32;   // 24
    for (int kt = 0; kt < NKT; kt++) {
        __syncthreads();   // previous compute done before overwriting smem
#pragma unroll
        for (int j = 0; j < 4; j++) {
            float4 h = hi4(ra[j]);
            *(float4*)(Ah + lrow * 36 + lcol + j * 4) = h;
            *(float4*)(Al + lrow * 36 + lcol + j * 4) = lo4(ra[j], h);
            h = hi4(rb[j]);
            *(float4*)(Bh + lrow * 36 + lcol + j * 4) = h;
            *(float4*)(Bl + lrow * 36 + lcol + j * 4) = lo4(rb[j], h);
        }
        __syncthreads();
        if (kt + 1 < NKT) {
#pragma unroll
            for (int j = 0; j < 4; j++) {
                ra[j] = *(const float4*)(Ag + (kt + 1) * 32 + j * 4);
                rb[j] = *(const float4*)(Wg + (kt + 1) * 32 + j * 4);
            }
        }
#pragma unroll
        for (int ks = 0; ks < 4; ks++) {
            unsigned afh[2][4], afl[2][4], bfh[8][2], bfl[8][2];
#pragma unroll
            for (int mt = 0; mt < 2; mt++) {
                const int base = (wm * 32 + mt * 16) * 36 + ks * 8;
                afh[mt][0] = __float_as_uint(Ah[base + gid * 36 + tig]);
                afh[mt][1] = __float_as_uint(Ah[base + (gid + 8) * 36 + tig]);
                afh[mt][2] = __float_as_uint(Ah[base + gid * 36 + tig + 4]);
                afh[mt][3] = __float_as_uint(Ah[base + (gid + 8) * 36 + tig + 4]);
                afl[mt][0] = __float_as_uint(Al[base + gid * 36 + tig]);
                afl[mt][1] = __float_as_uint(Al[base + (gid + 8) * 36 + tig]);
                afl[mt][2] = __float_as_uint(Al[base + gid * 36 + tig + 4]);
                afl[mt][3] = __float_as_uint(Al[base + (gid + 8) * 36 + tig + 4]);
            }
#pragma unroll
            for (int nt = 0; nt < 8; nt++) {
                const int base = (wn * 64 + nt * 8 + gid) * 36 + ks * 8;
                bfh[nt][0] = __float_as_uint(Bh[base + tig]);
                bfh[nt][1] = __float_as_uint(Bh[base + tig + 4]);
                bfl[nt][0] = __float_as_uint(Bl[base + tig]);
                bfl[nt][1] = __float_as_uint(Bl[base + tig + 4]);
            }
#pragma unroll
            for (int mt = 0; mt < 2; mt++)
#pragma unroll
                for (int nt = 0; nt < 8; nt++) {
                    mma8(acc[mt][nt], afh[mt], bfh[nt]);
                    mma8(acc[mt][nt], afh[mt], bfl[nt]);
                    mma8(acc[mt][nt], afl[mt], bfh[nt]);
                }
        }
    }

#pragma unroll
    for (int mt = 0; mt < 2; mt++) {
        const int n = by * 128 + wm * 32 + mt * 16 + gid;
#pragma unroll
        for (int nt = 0; nt < 8; nt++) {
            const int wcol = bxx * 128 + wn * 64 + nt * 8 + 2 * tig;
            const float b0 = bias[wcol], b1 = bias[wcol + 1];
            const int h_ = wcol >> 6, d_ = wcol & 63;
            float* dst = g_s + ((size_t)(sel * NHEADS + h_) * NSEQ + n) * HDIM + d_;
            *(float2*)dst = make_float2(acc[mt][nt][0] + b0, acc[mt][nt][1] + b1);
            *(float2*)(dst + 8 * HDIM) =
                make_float2(acc[mt][nt][2] + b0, acc[mt][nt][3] + b1);
        }
    }
}

// ---------------------------------------------------------------------------
// Flash attention (tf32x3) for one batch; ctx written straight into d_out.
// Grid (8 q-tiles, 12 heads), 256 threads (8 warps x 16 q-rows).
// ---------------------------------------------------------------------------
#define KPITCH 68
#define VPITCH 72
#define PPITCH 68
#define FLASH_SMEM ((2 * 64 * KPITCH + 2 * 64 * VPITCH + 2 * 8 * 16 * PPITCH) * 4) // 141312

__global__ __launch_bounds__(256) void flash_kernel(float* __restrict__ out, int group)
{
    extern __shared__ float sm[];
    float* ksh = sm;                         // [64][68]
    float* ksl = ksh + 64 * KPITCH;
    float* vsh = ksl + 64 * KPITCH;          // [64][72]
    float* vsl = vsh + 64 * VPITCH;
    float* psh = vsl + 64 * VPITCH;          // [8][16][68]
    float* psl = psh + 8 * 16 * PPITCH;

    const int h = blockIdx.y;
    const int q0 = blockIdx.x * 128;
    const int tid = threadIdx.x;
    const int lane = tid & 31;
    const int w = tid >> 5;
    const int gid = lane >> 2;
    const int tig = lane & 3;
    float* pwh = psh + w * 16 * PPITCH;
    float* pwl = psl + w * 16 * PPITCH;

    const float* qg = g_s + (size_t)h * NSEQ * HDIM;
    const float* kg = g_s + (size_t)(NHEADS + h) * NSEQ * HDIM;
    const float* vg = g_s + (size_t)(2 * NHEADS + h) * NSEQ * HDIM;

    const int r0 = q0 + w * 16 + gid;

    // Q fragments hi/lo (registers, reused for all 16 key tiles)
    unsigned qah[8][4], qal[8][4];
#pragma unroll
    for (int kk = 0; kk < 8; kk++) {
        const int c = kk * 8 + tig;
        float v0 = qg[(size_t)r0 * HDIM + c];
        float v1 = qg[(size_t)(r0 + 8) * HDIM + c];
        float v2 = qg[(size_t)r0 * HDIM + c + 4];
        float v3 = qg[(size_t)(r0 + 8) * HDIM + c + 4];
        float h0 = f2tff(v0), h1 = f2tff(v1), h2 = f2tff(v2), h3 = f2tff(v3);
        qah[kk][0] = __float_as_uint(h0); qal[kk][0] = f2tf(v0 - h0);
        qah[kk][1] = __float_as_uint(h1); qal[kk][1] = f2tf(v1 - h1);
        qah[kk][2] = __float_as_uint(h2); qal[kk][2] = f2tf(v2 - h2);
        qah[kk][3] = __float_as_uint(h3); qal[kk][3] = f2tf(v3 - h3);
    }

    float o[8][4];
#pragma unroll
    for (int dt = 0; dt < 8; dt++)
#pragma unroll
        for (int i = 0; i < 4; i++) o[dt][i] = 0.f;
    float m0 = -1e30f, m1 = -1e30f, l0 = 0.f, l1 = 0.f;

    for (int kt = 0; kt < 16; kt++) {
        __syncthreads();
#pragma unroll
        for (int i = 0; i < 4; i++) {
            const int idx = i * 256 + tid;          // 0..1023
            const int row = idx >> 4;
            const int c4 = (idx & 15) * 4;
            float4 kv = *(const float4*)(kg + (size_t)(kt * 64 + row) * HDIM + c4);
            float4 hh = hi4(kv);
            *(float4*)(ksh + row * KPITCH + c4) = hh;
            *(float4*)(ksl + row * KPITCH + c4) = lo4(kv, hh);
            float4 vv = *(const float4*)(vg + (size_t)(kt * 64 + row) * HDIM + c4);
            hh = hi4(vv);
            *(float4*)(vsh + row * VPITCH + c4) = hh;
            *(float4*)(vsl + row * VPITCH + c4) = lo4(vv, hh);
        }
        __syncthreads();

        // S = Q K^T (tf32x3)
        float s[8][4];
#pragma unroll
        for (int nt = 0; nt < 8; nt++)
#pragma unroll
            for (int i = 0; i < 4; i++) s[nt][i] = 0.f;
#pragma unroll
        for (int kk = 0; kk < 8; kk++) {
#pragma unroll
            for (int nt = 0; nt < 8; nt++) {
                const int base = (nt * 8 + gid) * KPITCH + kk * 8;
                unsigned bh[2], bl[2];
                bh[0] = __float_as_uint(ksh[base + tig]);
                bh[1] = __float_as_uint(ksh[base + tig + 4]);
                bl[0] = __float_as_uint(ksl[base + tig]);
                bl[1] = __float_as_uint(ksl[base + tig + 4]);
                mma8(s[nt], qah[kk], bh);
                mma8(s[nt], qah[kk], bl);
                mma8(s[nt], qal[kk], bh);
            }
        }

        // Online softmax
        float mx0 = -1e30f, mx1 = -1e30f;
#pragma unroll
        for (int nt = 0; nt < 8; nt++) {
            mx0 = fmaxf(mx0, fmaxf(s[nt][0], s[nt][1]));
            mx1 = fmaxf(mx1, fmaxf(s[nt][2], s[nt][3]));
        }
        mx0 = fmaxf(mx0, __shfl_xor_sync(0xffffffffu, mx0, 1));
        mx0 = fmaxf(mx0, __shfl_xor_sync(0xffffffffu, mx0, 2));
        mx1 = fmaxf(mx1, __shfl_xor_sync(0xffffffffu, mx1, 1));
        mx1 = fmaxf(mx1, __shfl_xor_sync(0xffffffffu, mx1, 2));
        const float nm0 = fmaxf(m0, mx0), nm1 = fmaxf(m1, mx1);
        const float sc0 = __expf(m0 - nm0), sc1 = __expf(m1 - nm1);
        float rs0 = 0.f, rs1 = 0.f;
#pragma unroll
        for (int nt = 0; nt < 8; nt++) {
            s[nt][0] = __expf(s[nt][0] - nm0); rs0 += s[nt][0];
            s[nt][1] = __expf(s[nt][1] - nm0); rs0 += s[nt][1];
            s[nt][2] = __expf(s[nt][2] - nm1); rs1 += s[nt][2];
            s[nt][3] = __expf(s[nt][3] - nm1); rs1 += s[nt][3];
        }
        rs0 += __shfl_xor_sync(0xffffffffu, rs0, 1);
        rs0 += __shfl_xor_sync(0xffffffffu, rs0, 2);
        rs1 += __shfl_xor_sync(0xffffffffu, rs1, 1);
        rs1 += __shfl_xor_sync(0xffffffffu, rs1, 2);
        l0 = l0 * sc0 + rs0;
        l1 = l1 * sc1 + rs1;
#pragma unroll
        for (int dt = 0; dt < 8; dt++) {
            o[dt][0] *= sc0; o[dt][1] *= sc0;
            o[dt][2] *= sc1; o[dt][3] *= sc1;
        }
        m0 = nm0; m1 = nm1;

        // P -> per-warp smem hi/lo, re-fragment as A for P*V
#pragma unroll
        for (int nt = 0; nt < 8; nt++) {
            float h0 = f2tff(s[nt][0]), h1 = f2tff(s[nt][1]);
            float h2 = f2tff(s[nt][2]), h3 = f2tff(s[nt][3]);
            const int c0 = nt * 8 + 2 * tig;
            pwh[gid * PPITCH + c0]           = h0;
            pwh[gid * PPITCH + c0 + 1]       = h1;
            pwh[(gid + 8) * PPITCH + c0]     = h2;
            pwh[(gid + 8) * PPITCH + c0 + 1] = h3;
            pwl[gid * PPITCH + c0]           = f2tff(s[nt][0] - h0);
            pwl[gid * PPITCH + c0 + 1]       = f2tff(s[nt][1] - h1);
            pwl[(gid + 8) * PPITCH + c0]     = f2tff(s[nt][2] - h2);
            pwl[(gid + 8) * PPITCH + c0 + 1] = f2tff(s[nt][3] - h3);
        }
        __syncwarp();

#pragma unroll
        for (int ks2 = 0; ks2 < 8; ks2++) {
            unsigned pah[4], pal[4];
            pah[0] = __float_as_uint(pwh[gid * PPITCH + ks2 * 8 + tig]);
            pah[1] = __float_as_uint(pwh[(gid + 8) * PPITCH + ks2 * 8 + tig]);
            pah[2] = __float_as_uint(pwh[gid * PPITCH + ks2 * 8 + tig + 4]);
            pah[3] = __float_as_uint(pwh[(gid + 8) * PPITCH + ks2 * 8 + tig + 4]);
            pal[0] = __float_as_uint(pwl[gid * PPITCH + ks2 * 8 + tig]);
            pal[1] = __float_as_uint(pwl[(gid + 8) * PPITCH + ks2 * 8 + tig]);
            pal[2] = __float_as_uint(pwl[gid * PPITCH + ks2 * 8 + tig + 4]);
            pal[3] = __float_as_uint(pwl[(gid + 8) * PPITCH + ks2 * 8 + tig + 4]);
#pragma unroll
            for (int dt = 0; dt < 8; dt++) {
                unsigned bh[2], bl[2];
                bh[0] = __float_as_uint(vsh[(ks2 * 8 + tig) * VPITCH + dt * 8 + gid]);
                bh[1] = __float_as_uint(vsh[(ks2 * 8 + tig + 4) * VPITCH + dt * 8 + gid]);
                bl[0] = __float_as_uint(vsl[(ks2 * 8 + tig) * VPITCH + dt * 8 + gid]);
                bl[1] = __float_as_uint(vsl[(ks2 * 8 + tig + 4) * VPITCH + dt * 8 + gid]);
                mma8(o[dt], pah, bh);
                mma8(o[dt], pah, bl);
                mma8(o[dt], pal, bh);
            }
        }
    }

    const float inv0 = 1.f / l0, inv1 = 1.f / l1;
    const size_t base0 = ((size_t)(group * NSEQ + r0)) * EMB + h * HDIM;
#pragma unroll
    for (int dt = 0; dt < 8; dt++) {
        const int d = dt * 8 + 2 * tig;
        *(float2*)(out + base0 + d) = make_float2(o[dt][0] * inv0, o[dt][1] * inv0);
        *(float2*)(out + base0 + (size_t)8 * EMB + d) =
            make_float2(o[dt][2] * inv1, o[dt][3] * inv1);
    }
}

// ---------------------------------------------------------------------------
// In-place output projection (tf32x3): io[m,:] = io[m,:] @ Wo^T + bo.
// CTA = 32-row strip x full 768 cols; all reads precede all writes.
// ---------------------------------------------------------------------------
__global__ __launch_bounds__(256) void outproj_kernel(
    float* __restrict__ io, const float* __restrict__ wo, const float* __restrict__ bo)
{
    __shared__ float Ash[32 * 36];
    __shared__ float Asl[32 * 36];

    const int tid = threadIdx.x;
    const int lane = tid & 31;
    const int w = tid >> 5;
    const int gid = lane >> 2;
    const int tig = lane & 3;
    const int strip = blockIdx.x * 32;

    const int arow = tid >> 3;
    const int acol = (tid & 7) * 4;
    const float* Ag = io + (size_t)(strip + arow) * EMB + acol;

    float acc[2][12][4];
#pragma unroll
    for (int mt = 0; mt < 2; mt++)
#pragma unroll
        for (int nt = 0; nt < 12; nt++)
#pragma unroll
            for (int i = 0; i < 4; i++) acc[mt][nt][i] = 0.f;

    float4 va = *(const float4*)(Ag);

    for (int kt = 0; kt < 24; kt++) {
        __syncthreads();
        {
            float4 hh = hi4(va);
            *(float4*)(Ash + arow * 36 + acol) = hh;
            *(float4*)(Asl + arow * 36 + acol) = lo4(va, hh);
        }
        __syncthreads();
        if (kt + 1 < 24) va = *(const float4*)(Ag + (kt + 1) * 32);

#pragma unroll
        for (int ks = 0; ks < 4; ks++) {
            unsigned afh[2][4], afl[2][4];
#pragma unroll
            for (int mt = 0; mt < 2; mt++) {
                const int base = (mt * 16) * 36 + ks * 8;
                afh[mt][0] = __float_as_uint(Ash[base + gid * 36 + tig]);
                afh[mt][1] = __float_as_uint(Ash[base + (gid + 8) * 36 + tig]);
                afh[mt][2] = __float_as_uint(Ash[base + gid * 36 + tig + 4]);
                afh[mt][3] = __float_as_uint(Ash[base + (gid + 8) * 36 + tig + 4]);
                afl[mt][0] = __float_as_uint(Asl[base + gid * 36 + tig]);
                afl[mt][1] = __float_as_uint(Asl[base + (gid + 8) * 36 + tig]);
                afl[mt][2] = __float_as_uint(Asl[base + gid * 36 + tig + 4]);
                afl[mt][3] = __float_as_uint(Asl[base + (gid + 8) * 36 + tig + 4]);
            }
#pragma unroll
            for (int nt = 0; nt < 12; nt++) {
                const int col = w * 96 + nt * 8 + gid;
                const float* bp = wo + (size_t)col * EMB + kt * 32 + ks * 8;
                float v0 = bp[tig], v1 = bp[tig + 4];
                float h0 = f2tff(v0), h1 = f2tff(v1);
                unsigned bh[2] = { __float_as_uint(h0), __float_as_uint(h1) };
                unsigned bl[2] = { f2tf(v0 - h0), f2tf(v1 - h1) };
#pragma unroll
                for (int mt = 0; mt < 2; mt++) {
                    mma8(acc[mt][nt], afh[mt], bh);
                    mma8(acc[mt][nt], afh[mt], bl);
                    mma8(acc[mt][nt], afl[mt], bh);
                }
            }
        }
    }

    __syncthreads();   // all in-place reads complete before any write

#pragma unroll
    for (int mt = 0; mt < 2; mt++) {
#pragma unroll
        for (int nt = 0; nt < 12; nt++) {
            const int row = strip + mt * 16 + gid;
            const int col = w * 96 + nt * 8 + 2 * tig;
            const float b0 = bo[col], b1 = bo[col + 1];
            *(float2*)(io + (size_t)row * EMB + col) =
                make_float2(acc[mt][nt][0] + b0, acc[mt][nt][1] + b1);
            *(float2*)(io + (size_t)(row + 8) * EMB + col) =
                make_float2(acc[mt][nt][2] + b0, acc[mt][nt][3] + b1);
        }
    }
}

extern "C" void kernel_launch(void* const* d_in, const int* in_sizes, int n_in,
                              void* d_out, int out_size)
{
    const float* x  = (const float*)d_in[0];
    const float* wq = (const float*)d_in[1];
    const float* bq = (const float*)d_in[2];
    const float* wk = (const float*)d_in[3];
    const float* bk = (const float*)d_in[4];
    const float* wv = (const float*)d_in[5];
    const float* bv = (const float*)d_in[6];
    const float* wo = (const float*)d_in[7];
    const float* bo = (const float*)d_in[8];
    float* out = (float*)d_out;

    cudaFuncSetAttribute(qkv_gemm_kernel, cudaFuncAttributeMaxDynamicSharedMemorySize, GEMM_SMEM);
    cudaFuncSetAttribute(flash_kernel, cudaFuncAttributeMaxDynamicSharedMemorySize, FLASH_SMEM);

    for (int g = 0; g < BATCH; g++) {
        dim3 ggrid(18, 8);
        qkv_gemm_kernel<<<ggrid, 256, GEMM_SMEM>>>(x, wq, bq, wk, bk, wv, bv, g);
        dim3 fgrid(8, NHEADS);
        flash_kernel<<<fgrid, 256, FLASH_SMEM>>>(out, g);
    }
    outproj_kernel<<<MTOT / 32, 256>>>(out, wo, bo);
}

// round 7
// speedup vs baseline: 1.3381x; 1.3381x over previous
#include <cuda_runtime.h>
#include <cstdint>
#include <cstdlib>

#define BATCH   8
#define NSEQ    1024
#define EMB     768
#define NHEADS  12
#define HDIM    64
#define MTOT    (BATCH * NSEQ)
#define HSTRIDE (NSEQ * HDIM)     // 65536

// Scratch: Q,K,V for TWO batches. 2*3*12*1024*64 floats = 18.9 MiB.
// Layout: [lb(2)][sel(3)][head(12)][n(1024)][d(64)]
__device__ float g_s[2 * 3 * NHEADS * NSEQ * HDIM];

namespace {
struct EagerLoad { EagerLoad() { setenv("CUDA_MODULE_LOADING", "EAGER", 1); } };
EagerLoad eager_load_instance_;
}

// ---------------------------------------------------------------------------
// tf32 helpers
// ---------------------------------------------------------------------------
__device__ __forceinline__ unsigned f2tf(float x) {
    unsigned r;
    asm("cvt.rna.tf32.f32 %0, %1;" : "=r"(r) : "f"(x));
    return r;
}
__device__ __forceinline__ float f2tff(float x) { return __uint_as_float(f2tf(x)); }

__device__ __forceinline__ void mma8(float* c, const unsigned* a, const unsigned* b) {
    asm volatile(
        "mma.sync.aligned.m16n8k8.row.col.f32.tf32.tf32.f32 "
        "{%0,%1,%2,%3}, {%4,%5,%6,%7}, {%8,%9}, {%0,%1,%2,%3};\n"
        : "+f"(c[0]), "+f"(c[1]), "+f"(c[2]), "+f"(c[3])
        : "r"(a[0]), "r"(a[1]), "r"(a[2]), "r"(a[3]), "r"(b[0]), "r"(b[1]));
}

__device__ __forceinline__ float4 hi4(float4 v) {
    return make_float4(f2tff(v.x), f2tff(v.y), f2tff(v.z), f2tff(v.w));
}
__device__ __forceinline__ float4 lo4(float4 v, float4 h) {
    return make_float4(f2tff(v.x - h.x), f2tff(v.y - h.y),
                       f2tff(v.z - h.z), f2tff(v.w - h.w));
}

// ---------------------------------------------------------------------------
// Fused QKV GEMM (tf32x3) for TWO batches: rows 0..2047 of x-group.
// Grid (18, 16): bx -> sel/coltile, by -> 128-row tile (8 per batch).
// ---------------------------------------------------------------------------
#define GEMM_SMEM (4 * 128 * 36 * 4)   // Ah, Al, Bh, Bl = 73728 B

__global__ __launch_bounds__(256) void qkv_gemm_kernel(
    const float* __restrict__ x,
    const float* __restrict__ wq, const float* __restrict__ bq,
    const float* __restrict__ wk, const float* __restrict__ bk,
    const float* __restrict__ wv, const float* __restrict__ bv,
    int group)
{
    extern __shared__ float sm[];
    float* Ah = sm;
    float* Al = sm + 128 * 36;
    float* Bh = sm + 2 * 128 * 36;
    float* Bl = sm + 3 * 128 * 36;

    const int bx = blockIdx.x;         // 0..17
    const int by = blockIdx.y;         // 0..15
    const int sel = bx / 6;
    const int bxx = bx % 6;
    const float* W    = (sel == 0) ? wq : (sel == 1) ? wk : wv;
    const float* bias = (sel == 0) ? bq : (sel == 1) ? bk : bv;
    const float* A = x + (size_t)(group * 2 * NSEQ) * EMB;

    const int tid = threadIdx.x;
    const int lane = tid & 31;
    const int w = tid >> 5;
    const int wm = w & 3;
    const int wn = w >> 2;
    const int gid = lane >> 2;
    const int tig = lane & 3;

    const int lrow = tid >> 1;
    const int lcol = (tid & 1) * 16;

    const float* Ag = A + (size_t)(by * 128 + lrow) * EMB + lcol;
    const float* Wg = W + (size_t)(bxx * 128 + lrow) * EMB + lcol;

    float acc[2][8][4];
#pragma unroll
    for (int mt = 0; mt < 2; mt++)
#pragma unroll
        for (int nt = 0; nt < 8; nt++)
#pragma unroll
            for (int i = 0; i < 4; i++) acc[mt][nt][i] = 0.f;

    float4 ra[4], rb[4];
#pragma unroll
    for (int j = 0; j < 4; j++) {
        ra[j] = *(const float4*)(Ag + j * 4);
        rb[j] = *(const float4*)(Wg + j * 4);
    }

    const int NKT = EMB / 32;   // 24
    for (int kt = 0; kt < NKT; kt++) {
        __syncthreads();
#pragma unroll
        for (int j = 0; j < 4; j++) {
            float4 h = hi4(ra[j]);
            *(float4*)(Ah + lrow * 36 + lcol + j * 4) = h;
            *(float4*)(Al + lrow * 36 + lcol + j * 4) = lo4(ra[j], h);
            h = hi4(rb[j]);
            *(float4*)(Bh + lrow * 36 + lcol + j * 4) = h;
            *(float4*)(Bl + lrow * 36 + lcol + j * 4) = lo4(rb[j], h);
        }
        __syncthreads();
        if (kt + 1 < NKT) {
#pragma unroll
            for (int j = 0; j < 4; j++) {
                ra[j] = *(const float4*)(Ag + (kt + 1) * 32 + j * 4);
                rb[j] = *(const float4*)(Wg + (kt + 1) * 32 + j * 4);
            }
        }
#pragma unroll
        for (int ks = 0; ks < 4; ks++) {
            unsigned afh[2][4], afl[2][4], bfh[8][2], bfl[8][2];
#pragma unroll
            for (int mt = 0; mt < 2; mt++) {
                const int base = (wm * 32 + mt * 16) * 36 + ks * 8;
                afh[mt][0] = __float_as_uint(Ah[base + gid * 36 + tig]);
                afh[mt][1] = __float_as_uint(Ah[base + (gid + 8) * 36 + tig]);
                afh[mt][2] = __float_as_uint(Ah[base + gid * 36 + tig + 4]);
                afh[mt][3] = __float_as_uint(Ah[base + (gid + 8) * 36 + tig + 4]);
                afl[mt][0] = __float_as_uint(Al[base + gid * 36 + tig]);
                afl[mt][1] = __float_as_uint(Al[base + (gid + 8) * 36 + tig]);
                afl[mt][2] = __float_as_uint(Al[base + gid * 36 + tig + 4]);
                afl[mt][3] = __float_as_uint(Al[base + (gid + 8) * 36 + tig + 4]);
            }
#pragma unroll
            for (int nt = 0; nt < 8; nt++) {
                const int base = (wn * 64 + nt * 8 + gid) * 36 + ks * 8;
                bfh[nt][0] = __float_as_uint(Bh[base + tig]);
                bfh[nt][1] = __float_as_uint(Bh[base + tig + 4]);
                bfl[nt][0] = __float_as_uint(Bl[base + tig]);
                bfl[nt][1] = __float_as_uint(Bl[base + tig + 4]);
            }
#pragma unroll
            for (int mt = 0; mt < 2; mt++)
#pragma unroll
                for (int nt = 0; nt < 8; nt++) {
                    mma8(acc[mt][nt], afh[mt], bfh[nt]);
                    mma8(acc[mt][nt], afh[mt], bfl[nt]);
                    mma8(acc[mt][nt], afl[mt], bfh[nt]);
                }
        }
    }

#pragma unroll
    for (int mt = 0; mt < 2; mt++) {
        const int grow = by * 128 + wm * 32 + mt * 16 + gid;   // 0..2047
        const int lb = grow >> 10;
        const int n = grow & 1023;
#pragma unroll
        for (int nt = 0; nt < 8; nt++) {
            const int wcol = bxx * 128 + wn * 64 + nt * 8 + 2 * tig;
            const float b0 = bias[wcol], b1 = bias[wcol + 1];
            const int h_ = wcol >> 6, d_ = wcol & 63;
            float* dst = g_s +
                (((size_t)(lb * 3 + sel) * NHEADS + h_) * NSEQ + n) * HDIM + d_;
            *(float2*)dst = make_float2(acc[mt][nt][0] + b0, acc[mt][nt][1] + b1);
            *(float2*)(dst + 8 * HDIM) =
                make_float2(acc[mt][nt][2] + b0, acc[mt][nt][3] + b1);
        }
    }
}

// ---------------------------------------------------------------------------
// Flash attention: S = QK^T in tf32x3, P*V in single tf32.
// Grid (16 q-tiles, 12 heads, 2 local batches); 128 threads (4 warps x 16 rows
// = 64 q-rows per CTA). Smem 70656 B -> 2-3 CTAs/SM.
// ---------------------------------------------------------------------------
#define KPITCH 68
#define VPITCH 72
#define PPITCH 68
#define FLASH_SMEM ((2 * 64 * KPITCH + 64 * VPITCH + 4 * 16 * PPITCH) * 4)  // 70656

__global__ __launch_bounds__(128) void flash_kernel(float* __restrict__ out, int group)
{
    extern __shared__ float sm[];
    float* ksh = sm;                         // [64][68]
    float* ksl = ksh + 64 * KPITCH;          // [64][68]
    float* vsh = ksl + 64 * KPITCH;          // [64][72]
    float* psh = vsh + 64 * VPITCH;          // [4][16][68]

    const int h = blockIdx.y;
    const int lb = blockIdx.z;
    const int q0 = blockIdx.x * 64;
    const int tid = threadIdx.x;
    const int lane = tid & 31;
    const int w = tid >> 5;                  // 0..3
    const int gid = lane >> 2;
    const int tig = lane & 3;
    float* pw = psh + w * 16 * PPITCH;

    const float* qg = g_s + ((size_t)(lb * 3 + 0) * NHEADS + h) * HSTRIDE;
    const float* kg = g_s + ((size_t)(lb * 3 + 1) * NHEADS + h) * HSTRIDE;
    const float* vg = g_s + ((size_t)(lb * 3 + 2) * NHEADS + h) * HSTRIDE;

    const int r0 = q0 + w * 16 + gid;

    // Q fragments hi/lo in registers (reused across all 16 key tiles)
    unsigned qah[8][4], qal[8][4];
#pragma unroll
    for (int kk = 0; kk < 8; kk++) {
        const int c = kk * 8 + tig;
        float v0 = qg[(size_t)r0 * HDIM + c];
        float v1 = qg[(size_t)(r0 + 8) * HDIM + c];
        float v2 = qg[(size_t)r0 * HDIM + c + 4];
        float v3 = qg[(size_t)(r0 + 8) * HDIM + c + 4];
        float h0 = f2tff(v0), h1 = f2tff(v1), h2 = f2tff(v2), h3 = f2tff(v3);
        qah[kk][0] = __float_as_uint(h0); qal[kk][0] = f2tf(v0 - h0);
        qah[kk][1] = __float_as_uint(h1); qal[kk][1] = f2tf(v1 - h1);
        qah[kk][2] = __float_as_uint(h2); qal[kk][2] = f2tf(v2 - h2);
        qah[kk][3] = __float_as_uint(h3); qal[kk][3] = f2tf(v3 - h3);
    }

    float o[8][4];
#pragma unroll
    for (int dt = 0; dt < 8; dt++)
#pragma unroll
        for (int i = 0; i < 4; i++) o[dt][i] = 0.f;
    float m0 = -1e30f, m1 = -1e30f, l0 = 0.f, l1 = 0.f;

    for (int kt = 0; kt < 16; kt++) {
        __syncthreads();
        // K hi/lo + V hi tile load (64 rows x 64 cols, 128 threads)
#pragma unroll
        for (int i = 0; i < 8; i++) {
            const int idx = i * 128 + tid;          // 0..1023
            const int row = idx >> 4;
            const int c4 = (idx & 15) * 4;
            float4 kv = *(const float4*)(kg + (size_t)(kt * 64 + row) * HDIM + c4);
            float4 hh = hi4(kv);
            *(float4*)(ksh + row * KPITCH + c4) = hh;
            *(float4*)(ksl + row * KPITCH + c4) = lo4(kv, hh);
            float4 vv = *(const float4*)(vg + (size_t)(kt * 64 + row) * HDIM + c4);
            *(float4*)(vsh + row * VPITCH + c4) = hi4(vv);
        }
        __syncthreads();

        // S = Q K^T (tf32x3)
        float s[8][4];
#pragma unroll
        for (int nt = 0; nt < 8; nt++)
#pragma unroll
            for (int i = 0; i < 4; i++) s[nt][i] = 0.f;
#pragma unroll
        for (int kk = 0; kk < 8; kk++) {
#pragma unroll
            for (int nt = 0; nt < 8; nt++) {
                const int base = (nt * 8 + gid) * KPITCH + kk * 8;
                unsigned bh[2], bl[2];
                bh[0] = __float_as_uint(ksh[base + tig]);
                bh[1] = __float_as_uint(ksh[base + tig + 4]);
                bl[0] = __float_as_uint(ksl[base + tig]);
                bl[1] = __float_as_uint(ksl[base + tig + 4]);
                mma8(s[nt], qah[kk], bh);
                mma8(s[nt], qah[kk], bl);
                mma8(s[nt], qal[kk], bh);
            }
        }

        // Online softmax
        float mx0 = -1e30f, mx1 = -1e30f;
#pragma unroll
        for (int nt = 0; nt < 8; nt++) {
            mx0 = fmaxf(mx0, fmaxf(s[nt][0], s[nt][1]));
            mx1 = fmaxf(mx1, fmaxf(s[nt][2], s[nt][3]));
        }
        mx0 = fmaxf(mx0, __shfl_xor_sync(0xffffffffu, mx0, 1));
        mx0 = fmaxf(mx0, __shfl_xor_sync(0xffffffffu, mx0, 2));
        mx1 = fmaxf(mx1, __shfl_xor_sync(0xffffffffu, mx1, 1));
        mx1 = fmaxf(mx1, __shfl_xor_sync(0xffffffffu, mx1, 2));
        const float nm0 = fmaxf(m0, mx0), nm1 = fmaxf(m1, mx1);
        const float sc0 = __expf(m0 - nm0), sc1 = __expf(m1 - nm1);
        float rs0 = 0.f, rs1 = 0.f;
#pragma unroll
        for (int nt = 0; nt < 8; nt++) {
            s[nt][0] = __expf(s[nt][0] - nm0); rs0 += s[nt][0];
            s[nt][1] = __expf(s[nt][1] - nm0); rs0 += s[nt][1];
            s[nt][2] = __expf(s[nt][2] - nm1); rs1 += s[nt][2];
            s[nt][3] = __expf(s[nt][3] - nm1); rs1 += s[nt][3];
        }
        rs0 += __shfl_xor_sync(0xffffffffu, rs0, 1);
        rs0 += __shfl_xor_sync(0xffffffffu, rs0, 2);
        rs1 += __shfl_xor_sync(0xffffffffu, rs1, 1);
        rs1 += __shfl_xor_sync(0xffffffffu, rs1, 2);
        l0 = l0 * sc0 + rs0;
        l1 = l1 * sc1 + rs1;
#pragma unroll
        for (int dt = 0; dt < 8; dt++) {
            o[dt][0] *= sc0; o[dt][1] *= sc0;
            o[dt][2] *= sc1; o[dt][3] *= sc1;
        }
        m0 = nm0; m1 = nm1;

        // P -> per-warp smem (single tf32), re-fragment as A for P*V
#pragma unroll
        for (int nt = 0; nt < 8; nt++) {
            const int c0 = nt * 8 + 2 * tig;
            pw[gid * PPITCH + c0]           = f2tff(s[nt][0]);
            pw[gid * PPITCH + c0 + 1]       = f2tff(s[nt][1]);
            pw[(gid + 8) * PPITCH + c0]     = f2tff(s[nt][2]);
            pw[(gid + 8) * PPITCH + c0 + 1] = f2tff(s[nt][3]);
        }
        __syncwarp();

#pragma unroll
        for (int ks2 = 0; ks2 < 8; ks2++) {
            unsigned pa[4];
            pa[0] = __float_as_uint(pw[gid * PPITCH + ks2 * 8 + tig]);
            pa[1] = __float_as_uint(pw[(gid + 8) * PPITCH + ks2 * 8 + tig]);
            pa[2] = __float_as_uint(pw[gid * PPITCH + ks2 * 8 + tig + 4]);
            pa[3] = __float_as_uint(pw[(gid + 8) * PPITCH + ks2 * 8 + tig + 4]);
#pragma unroll
            for (int dt = 0; dt < 8; dt++) {
                unsigned bb[2];
                bb[0] = __float_as_uint(vsh[(ks2 * 8 + tig) * VPITCH + dt * 8 + gid]);
                bb[1] = __float_as_uint(vsh[(ks2 * 8 + tig + 4) * VPITCH + dt * 8 + gid]);
                mma8(o[dt], pa, bb);
            }
        }
    }

    const float inv0 = 1.f / l0, inv1 = 1.f / l1;
    const size_t base0 =
        ((size_t)((group * 2 + lb) * NSEQ + r0)) * EMB + h * HDIM;
#pragma unroll
    for (int dt = 0; dt < 8; dt++) {
        const int d = dt * 8 + 2 * tig;
        *(float2*)(out + base0 + d) = make_float2(o[dt][0] * inv0, o[dt][1] * inv0);
        *(float2*)(out + base0 + (size_t)8 * EMB + d) =
            make_float2(o[dt][2] * inv1, o[dt][3] * inv1);
    }
}

// ---------------------------------------------------------------------------
// In-place output projection (tf32x2: ctx split hi/lo, Wo single tf32).
// CTA = 32-row strip x full 768 cols; all reads precede all writes.
// ---------------------------------------------------------------------------
__global__ __launch_bounds__(256) void outproj_kernel(
    float* __restrict__ io, const float* __restrict__ wo, const float* __restrict__ bo)
{
    __shared__ float Ash[32 * 36];
    __shared__ float Asl[32 * 36];

    const int tid = threadIdx.x;
    const int lane = tid & 31;
    const int w = tid >> 5;
    const int gid = lane >> 2;
    const int tig = lane & 3;
    const int strip = blockIdx.x * 32;

    const int arow = tid >> 3;
    const int acol = (tid & 7) * 4;
    const float* Ag = io + (size_t)(strip + arow) * EMB + acol;

    float acc[2][12][4];
#pragma unroll
    for (int mt = 0; mt < 2; mt++)
#pragma unroll
        for (int nt = 0; nt < 12; nt++)
#pragma unroll
            for (int i = 0; i < 4; i++) acc[mt][nt][i] = 0.f;

    float4 va = *(const float4*)(Ag);

    for (int kt = 0; kt < 24; kt++) {
        __syncthreads();
        {
            float4 hh = hi4(va);
            *(float4*)(Ash + arow * 36 + acol) = hh;
            *(float4*)(Asl + arow * 36 + acol) = lo4(va, hh);
        }
        __syncthreads();
        if (kt + 1 < 24) va = *(const float4*)(Ag + (kt + 1) * 32);

#pragma unroll
        for (int ks = 0; ks < 4; ks++) {
            unsigned afh[2][4], afl[2][4];
#pragma unroll
            for (int mt = 0; mt < 2; mt++) {
                const int base = (mt * 16) * 36 + ks * 8;
                afh[mt][0] = __float_as_uint(Ash[base + gid * 36 + tig]);
                afh[mt][1] = __float_as_uint(Ash[base + (gid + 8) * 36 + tig]);
                afh[mt][2] = __float_as_uint(Ash[base + gid * 36 + tig + 4]);
                afh[mt][3] = __float_as_uint(Ash[base + (gid + 8) * 36 + tig + 4]);
                afl[mt][0] = __float_as_uint(Asl[base + gid * 36 + tig]);
                afl[mt][1] = __float_as_uint(Asl[base + (gid + 8) * 36 + tig]);
                afl[mt][2] = __float_as_uint(Asl[base + gid * 36 + tig + 4]);
                afl[mt][3] = __float_as_uint(Asl[base + (gid + 8) * 36 + tig + 4]);
            }
#pragma unroll
            for (int nt = 0; nt < 12; nt++) {
                const int col = w * 96 + nt * 8 + gid;
                const float* bp = wo + (size_t)col * EMB + kt * 32 + ks * 8;
                unsigned bh[2];
                bh[0] = f2tf(bp[tig]);
                bh[1] = f2tf(bp[tig + 4]);
#pragma unroll
                for (int mt = 0; mt < 2; mt++) {
                    mma8(acc[mt][nt], afh[mt], bh);
                    mma8(acc[mt][nt], afl[mt], bh);
                }
            }
        }
    }

    __syncthreads();   // all in-place reads complete before any write

#pragma unroll
    for (int mt = 0; mt < 2; mt++) {
#pragma unroll
        for (int nt = 0; nt < 12; nt++) {
            const int row = strip + mt * 16 + gid;
            const int col = w * 96 + nt * 8 + 2 * tig;
            const float b0 = bo[col], b1 = bo[col + 1];
            *(float2*)(io + (size_t)row * EMB + col) =
                make_float2(acc[mt][nt][0] + b0, acc[mt][nt][1] + b1);
            *(float2*)(io + (size_t)(row + 8) * EMB + col) =
                make_float2(acc[mt][nt][2] + b0, acc[mt][nt][3] + b1);
        }
    }
}

extern "C" void kernel_launch(void* const* d_in, const int* in_sizes, int n_in,
                              void* d_out, int out_size)
{
    const float* x  = (const float*)d_in[0];
    const float* wq = (const float*)d_in[1];
    const float* bq = (const float*)d_in[2];
    const float* wk = (const float*)d_in[3];
    const float* bk = (const float*)d_in[4];
    const float* wv = (const float*)d_in[5];
    const float* bv = (const float*)d_in[6];
    const float* wo = (const float*)d_in[7];
    const float* bo = (const float*)d_in[8];
    float* out = (float*)d_out;

    cudaFuncSetAttribute(qkv_gemm_kernel, cudaFuncAttributeMaxDynamicSharedMemorySize, GEMM_SMEM);
    cudaFuncSetAttribute(flash_kernel, cudaFuncAttributeMaxDynamicSharedMemorySize, FLASH_SMEM);

    for (int g = 0; g < 4; g++) {
        dim3 ggrid(18, 16);
        qkv_gemm_kernel<<<ggrid, 256, GEMM_SMEM>>>(x, wq, bq, wk, bk, wv, bv, g);
        dim3 fgrid(16, NHEADS, 2);
        flash_kernel<<<fgrid, 128, FLASH_SMEM>>>(out, g);
    }
    outproj_kernel<<<MTOT / 32, 256>>>(out, wo, bo);
}

// round 8
// speedup vs baseline: 1.4345x; 1.0721x over previous
#include <cuda_runtime.h>
#include <cstdint>
#include <cstdlib>

#define BATCH   8
#define NSEQ    1024
#define EMB     768
#define NHEADS  12
#define HDIM    64
#define MTOT    (BATCH * NSEQ)
#define HSTRIDE (NSEQ * HDIM)     // 65536

// Scratch: Q,K,V for TWO batches. 18.9 MiB. [lb(2)][sel(3)][head][n][d]
__device__ float g_s[2 * 3 * NHEADS * NSEQ * HDIM];

namespace {
struct EagerLoad { EagerLoad() { setenv("CUDA_MODULE_LOADING", "EAGER", 1); } };
EagerLoad eager_load_instance_;
}

// ---------------------------------------------------------------------------
// tf32 helpers
// ---------------------------------------------------------------------------
__device__ __forceinline__ unsigned f2tf(float x) {
    unsigned r;
    asm("cvt.rna.tf32.f32 %0, %1;" : "=r"(r) : "f"(x));
    return r;
}
__device__ __forceinline__ float f2tff(float x) { return __uint_as_float(f2tf(x)); }

__device__ __forceinline__ void mma8(float* c, const unsigned* a, const unsigned* b) {
    asm volatile(
        "mma.sync.aligned.m16n8k8.row.col.f32.tf32.tf32.f32 "
        "{%0,%1,%2,%3}, {%4,%5,%6,%7}, {%8,%9}, {%0,%1,%2,%3};\n"
        : "+f"(c[0]), "+f"(c[1]), "+f"(c[2]), "+f"(c[3])
        : "r"(a[0]), "r"(a[1]), "r"(a[2]), "r"(a[3]), "r"(b[0]), "r"(b[1]));
}

__device__ __forceinline__ float4 hi4(float4 v) {
    return make_float4(f2tff(v.x), f2tff(v.y), f2tff(v.z), f2tff(v.w));
}

// ---------------------------------------------------------------------------
// Fused QKV GEMM (tf32x2: x hi+lo, W hi only) for TWO batches.
// Grid (18, 16). Double-buffered smem: A raw fp32, B pre-rounded tf32.
// A hi/lo derived at fragment-load time.
// ---------------------------------------------------------------------------
#define GEMM_SMEM (4 * 128 * 36 * 4)   // Araw[2] + Bh[2] = 73728 B

__global__ __launch_bounds__(256) void qkv_gemm_kernel(
    const float* __restrict__ x,
    const float* __restrict__ wq, const float* __restrict__ bq,
    const float* __restrict__ wk, const float* __restrict__ bk,
    const float* __restrict__ wv, const float* __restrict__ bv,
    int group)
{
    extern __shared__ float sm[];
    float* Ar = sm;                    // [2][128*36] raw fp32
    float* Bh = sm + 2 * 128 * 36;     // [2][128*36] tf32-hi

    const int bx = blockIdx.x;         // 0..17
    const int by = blockIdx.y;         // 0..15
    const int sel = bx / 6;
    const int bxx = bx % 6;
    const float* W    = (sel == 0) ? wq : (sel == 1) ? wk : wv;
    const float* bias = (sel == 0) ? bq : (sel == 1) ? bk : bv;
    const float* A = x + (size_t)(group * 2 * NSEQ) * EMB;

    const int tid = threadIdx.x;
    const int lane = tid & 31;
    const int w = tid >> 5;
    const int wm = w & 3;
    const int wn = w >> 2;
    const int gid = lane >> 2;
    const int tig = lane & 3;

    const int lrow = tid >> 1;
    const int lcol = (tid & 1) * 16;

    const float* Ag = A + (size_t)(by * 128 + lrow) * EMB + lcol;
    const float* Wg = W + (size_t)(bxx * 128 + lrow) * EMB + lcol;

    float acc[2][8][4];
#pragma unroll
    for (int mt = 0; mt < 2; mt++)
#pragma unroll
        for (int nt = 0; nt < 8; nt++)
#pragma unroll
            for (int i = 0; i < 4; i++) acc[mt][nt][i] = 0.f;

    float4 ra[4], rb[4];
#pragma unroll
    for (int j = 0; j < 4; j++) {
        ra[j] = *(const float4*)(Ag + j * 4);
        rb[j] = *(const float4*)(Wg + j * 4);
    }
#pragma unroll
    for (int j = 0; j < 4; j++) {
        *(float4*)(Ar + lrow * 36 + lcol + j * 4) = ra[j];
        *(float4*)(Bh + lrow * 36 + lcol + j * 4) = hi4(rb[j]);
    }
    __syncthreads();

    const int NKT = EMB / 32;   // 24
    for (int kt = 0; kt < NKT; kt++) {
        const int cur = kt & 1;
        if (kt + 1 < NKT) {
#pragma unroll
            for (int j = 0; j < 4; j++) {
                ra[j] = *(const float4*)(Ag + (kt + 1) * 32 + j * 4);
                rb[j] = *(const float4*)(Wg + (kt + 1) * 32 + j * 4);
            }
        }
        const float* Ab = Ar + cur * 128 * 36;
        const float* Bb = Bh + cur * 128 * 36;
#pragma unroll
        for (int ks = 0; ks < 4; ks++) {
            unsigned afh[2][4], afl[2][4], bfh[8][2];
#pragma unroll
            for (int mt = 0; mt < 2; mt++) {
                const int base = (wm * 32 + mt * 16) * 36 + ks * 8;
                float a0 = Ab[base + gid * 36 + tig];
                float a1 = Ab[base + (gid + 8) * 36 + tig];
                float a2 = Ab[base + gid * 36 + tig + 4];
                float a3 = Ab[base + (gid + 8) * 36 + tig + 4];
                float h0 = f2tff(a0), h1 = f2tff(a1), h2 = f2tff(a2), h3 = f2tff(a3);
                afh[mt][0] = __float_as_uint(h0); afl[mt][0] = f2tf(a0 - h0);
                afh[mt][1] = __float_as_uint(h1); afl[mt][1] = f2tf(a1 - h1);
                afh[mt][2] = __float_as_uint(h2); afl[mt][2] = f2tf(a2 - h2);
                afh[mt][3] = __float_as_uint(h3); afl[mt][3] = f2tf(a3 - h3);
            }
#pragma unroll
            for (int nt = 0; nt < 8; nt++) {
                const int base = (wn * 64 + nt * 8 + gid) * 36 + ks * 8;
                bfh[nt][0] = __float_as_uint(Bb[base + tig]);
                bfh[nt][1] = __float_as_uint(Bb[base + tig + 4]);
            }
#pragma unroll
            for (int mt = 0; mt < 2; mt++)
#pragma unroll
                for (int nt = 0; nt < 8; nt++) {
                    mma8(acc[mt][nt], afh[mt], bfh[nt]);
                    mma8(acc[mt][nt], afl[mt], bfh[nt]);
                }
        }
        if (kt + 1 < NKT) {
            const int nxt = cur ^ 1;
#pragma unroll
            for (int j = 0; j < 4; j++) {
                *(float4*)(Ar + nxt * 128 * 36 + lrow * 36 + lcol + j * 4) = ra[j];
                *(float4*)(Bh + nxt * 128 * 36 + lrow * 36 + lcol + j * 4) = hi4(rb[j]);
            }
            __syncthreads();
        }
    }

#pragma unroll
    for (int mt = 0; mt < 2; mt++) {
        const int grow = by * 128 + wm * 32 + mt * 16 + gid;   // 0..2047
        const int lb = grow >> 10;
        const int n = grow & 1023;
#pragma unroll
        for (int nt = 0; nt < 8; nt++) {
            const int wcol = bxx * 128 + wn * 64 + nt * 8 + 2 * tig;
            const float b0 = bias[wcol], b1 = bias[wcol + 1];
            const int h_ = wcol >> 6, d_ = wcol & 63;
            float* dst = g_s +
                (((size_t)(lb * 3 + sel) * NHEADS + h_) * NSEQ + n) * HDIM + d_;
            *(float2*)dst = make_float2(acc[mt][nt][0] + b0, acc[mt][nt][1] + b1);
            *(float2*)(dst + 8 * HDIM) =
                make_float2(acc[mt][nt][2] + b0, acc[mt][nt][3] + b1);
        }
    }
}

// ---------------------------------------------------------------------------
// Flash attention: S = QK^T tf32x3 (K stored RAW, hi/lo split at fragment
// load — halves K LDS and removes tile-load cvts), P*V single tf32.
// Grid (16, 12, 2); 128 threads. Smem 53248 B -> 3 CTAs/SM.
// ---------------------------------------------------------------------------
#define KPITCH 68
#define VPITCH 72
#define PPITCH 68
#define FLASH_SMEM ((64 * KPITCH + 64 * VPITCH + 4 * 16 * PPITCH) * 4)  // 53248

__global__ __launch_bounds__(128) void flash_kernel(float* __restrict__ out, int group)
{
    extern __shared__ float sm[];
    float* ksr = sm;                         // [64][68] raw K
    float* vsh = ksr + 64 * KPITCH;          // [64][72] tf32-hi V
    float* psh = vsh + 64 * VPITCH;          // [4][16][68] P

    const int h = blockIdx.y;
    const int lb = blockIdx.z;
    const int q0 = blockIdx.x * 64;
    const int tid = threadIdx.x;
    const int lane = tid & 31;
    const int w = tid >> 5;                  // 0..3
    const int gid = lane >> 2;
    const int tig = lane & 3;
    float* pw = psh + w * 16 * PPITCH;

    const float* qg = g_s + ((size_t)(lb * 3 + 0) * NHEADS + h) * HSTRIDE;
    const float* kg = g_s + ((size_t)(lb * 3 + 1) * NHEADS + h) * HSTRIDE;
    const float* vg = g_s + ((size_t)(lb * 3 + 2) * NHEADS + h) * HSTRIDE;

    const int r0 = q0 + w * 16 + gid;

    // Q fragments hi/lo in registers (reused across all 16 key tiles)
    unsigned qah[8][4], qal[8][4];
#pragma unroll
    for (int kk = 0; kk < 8; kk++) {
        const int c = kk * 8 + tig;
        float v0 = qg[(size_t)r0 * HDIM + c];
        float v1 = qg[(size_t)(r0 + 8) * HDIM + c];
        float v2 = qg[(size_t)r0 * HDIM + c + 4];
        float v3 = qg[(size_t)(r0 + 8) * HDIM + c + 4];
        float h0 = f2tff(v0), h1 = f2tff(v1), h2 = f2tff(v2), h3 = f2tff(v3);
        qah[kk][0] = __float_as_uint(h0); qal[kk][0] = f2tf(v0 - h0);
        qah[kk][1] = __float_as_uint(h1); qal[kk][1] = f2tf(v1 - h1);
        qah[kk][2] = __float_as_uint(h2); qal[kk][2] = f2tf(v2 - h2);
        qah[kk][3] = __float_as_uint(h3); qal[kk][3] = f2tf(v3 - h3);
    }

    float o[8][4];
#pragma unroll
    for (int dt = 0; dt < 8; dt++)
#pragma unroll
        for (int i = 0; i < 4; i++) o[dt][i] = 0.f;
    float m0 = -1e30f, m1 = -1e30f, l0 = 0.f, l1 = 0.f;

    for (int kt = 0; kt < 16; kt++) {
        __syncthreads();
        // Tile load: K raw (no cvt), V hi
#pragma unroll
        for (int i = 0; i < 8; i++) {
            const int idx = i * 128 + tid;          // 0..1023
            const int row = idx >> 4;
            const int c4 = (idx & 15) * 4;
            *(float4*)(ksr + row * KPITCH + c4) =
                *(const float4*)(kg + (size_t)(kt * 64 + row) * HDIM + c4);
            float4 vv = *(const float4*)(vg + (size_t)(kt * 64 + row) * HDIM + c4);
            *(float4*)(vsh + row * VPITCH + c4) = hi4(vv);
        }
        __syncthreads();

        // S = Q K^T (tf32x3; K hi/lo derived from raw at fragment load)
        float s[8][4];
#pragma unroll
        for (int nt = 0; nt < 8; nt++)
#pragma unroll
            for (int i = 0; i < 4; i++) s[nt][i] = 0.f;
#pragma unroll
        for (int kk = 0; kk < 8; kk++) {
#pragma unroll
            for (int nt = 0; nt < 8; nt++) {
                const int base = (nt * 8 + gid) * KPITCH + kk * 8;
                float k0 = ksr[base + tig];
                float k1 = ksr[base + tig + 4];
                float h0 = f2tff(k0), h1 = f2tff(k1);
                unsigned bh[2] = { __float_as_uint(h0), __float_as_uint(h1) };
                unsigned bl[2] = { f2tf(k0 - h0), f2tf(k1 - h1) };
                mma8(s[nt], qah[kk], bh);
                mma8(s[nt], qah[kk], bl);
                mma8(s[nt], qal[kk], bh);
            }
        }

        // Online softmax
        float mx0 = -1e30f, mx1 = -1e30f;
#pragma unroll
        for (int nt = 0; nt < 8; nt++) {
            mx0 = fmaxf(mx0, fmaxf(s[nt][0], s[nt][1]));
            mx1 = fmaxf(mx1, fmaxf(s[nt][2], s[nt][3]));
        }
        mx0 = fmaxf(mx0, __shfl_xor_sync(0xffffffffu, mx0, 1));
        mx0 = fmaxf(mx0, __shfl_xor_sync(0xffffffffu, mx0, 2));
        mx1 = fmaxf(mx1, __shfl_xor_sync(0xffffffffu, mx1, 1));
        mx1 = fmaxf(mx1, __shfl_xor_sync(0xffffffffu, mx1, 2));
        const float nm0 = fmaxf(m0, mx0), nm1 = fmaxf(m1, mx1);
        const float sc0 = __expf(m0 - nm0), sc1 = __expf(m1 - nm1);
        float rs0 = 0.f, rs1 = 0.f;
#pragma unroll
        for (int nt = 0; nt < 8; nt++) {
            s[nt][0] = __expf(s[nt][0] - nm0); rs0 += s[nt][0];
            s[nt][1] = __expf(s[nt][1] - nm0); rs0 += s[nt][1];
            s[nt][2] = __expf(s[nt][2] - nm1); rs1 += s[nt][2];
            s[nt][3] = __expf(s[nt][3] - nm1); rs1 += s[nt][3];
        }
        rs0 += __shfl_xor_sync(0xffffffffu, rs0, 1);
        rs0 += __shfl_xor_sync(0xffffffffu, rs0, 2);
        rs1 += __shfl_xor_sync(0xffffffffu, rs1, 1);
        rs1 += __shfl_xor_sync(0xffffffffu, rs1, 2);
        l0 = l0 * sc0 + rs0;
        l1 = l1 * sc1 + rs1;
#pragma unroll
        for (int dt = 0; dt < 8; dt++) {
            o[dt][0] *= sc0; o[dt][1] *= sc0;
            o[dt][2] *= sc1; o[dt][3] *= sc1;
        }
        m0 = nm0; m1 = nm1;

        // P -> per-warp smem (single tf32), re-fragment as A for P*V
#pragma unroll
        for (int nt = 0; nt < 8; nt++) {
            const int c0 = nt * 8 + 2 * tig;
            pw[gid * PPITCH + c0]           = f2tff(s[nt][0]);
            pw[gid * PPITCH + c0 + 1]       = f2tff(s[nt][1]);
            pw[(gid + 8) * PPITCH + c0]     = f2tff(s[nt][2]);
            pw[(gid + 8) * PPITCH + c0 + 1] = f2tff(s[nt][3]);
        }
        __syncwarp();

#pragma unroll
        for (int ks2 = 0; ks2 < 8; ks2++) {
            unsigned pa[4];
            pa[0] = __float_as_uint(pw[gid * PPITCH + ks2 * 8 + tig]);
            pa[1] = __float_as_uint(pw[(gid + 8) * PPITCH + ks2 * 8 + tig]);
            pa[2] = __float_as_uint(pw[gid * PPITCH + ks2 * 8 + tig + 4]);
            pa[3] = __float_as_uint(pw[(gid + 8) * PPITCH + ks2 * 8 + tig + 4]);
#pragma unroll
            for (int dt = 0; dt < 8; dt++) {
                unsigned bb[2];
                bb[0] = __float_as_uint(vsh[(ks2 * 8 + tig) * VPITCH + dt * 8 + gid]);
                bb[1] = __float_as_uint(vsh[(ks2 * 8 + tig + 4) * VPITCH + dt * 8 + gid]);
                mma8(o[dt], pa, bb);
            }
        }
    }

    const float inv0 = 1.f / l0, inv1 = 1.f / l1;
    const size_t base0 =
        ((size_t)((group * 2 + lb) * NSEQ + r0)) * EMB + h * HDIM;
#pragma unroll
    for (int dt = 0; dt < 8; dt++) {
        const int d = dt * 8 + 2 * tig;
        *(float2*)(out + base0 + d) = make_float2(o[dt][0] * inv0, o[dt][1] * inv0);
        *(float2*)(out + base0 + (size_t)8 * EMB + d) =
            make_float2(o[dt][2] * inv1, o[dt][3] * inv1);
    }
}

// ---------------------------------------------------------------------------
// In-place output projection (tf32x2: ctx split hi/lo, Wo single tf32).
// ---------------------------------------------------------------------------
__global__ __launch_bounds__(256) void outproj_kernel(
    float* __restrict__ io, const float* __restrict__ wo, const float* __restrict__ bo)
{
    __shared__ float Ash[32 * 36];
    __shared__ float Asl[32 * 36];

    const int tid = threadIdx.x;
    const int lane = tid & 31;
    const int w = tid >> 5;
    const int gid = lane >> 2;
    const int tig = lane & 3;
    const int strip = blockIdx.x * 32;

    const int arow = tid >> 3;
    const int acol = (tid & 7) * 4;
    const float* Ag = io + (size_t)(strip + arow) * EMB + acol;

    float acc[2][12][4];
#pragma unroll
    for (int mt = 0; mt < 2; mt++)
#pragma unroll
        for (int nt = 0; nt < 12; nt++)
#pragma unroll
            for (int i = 0; i < 4; i++) acc[mt][nt][i] = 0.f;

    float4 va = *(const float4*)(Ag);

    for (int kt = 0; kt < 24; kt++) {
        __syncthreads();
        {
            float4 hh = hi4(va);
            *(float4*)(Ash + arow * 36 + acol) = hh;
            *(float4*)(Asl + arow * 36 + acol) = make_float4(
                f2tff(va.x - hh.x), f2tff(va.y - hh.y),
                f2tff(va.z - hh.z), f2tff(va.w - hh.w));
        }
        __syncthreads();
        if (kt + 1 < 24) va = *(const float4*)(Ag + (kt + 1) * 32);

#pragma unroll
        for (int ks = 0; ks < 4; ks++) {
            unsigned afh[2][4], afl[2][4];
#pragma unroll
            for (int mt = 0; mt < 2; mt++) {
                const int base = (mt * 16) * 36 + ks * 8;
                afh[mt][0] = __float_as_uint(Ash[base + gid * 36 + tig]);
                afh[mt][1] = __float_as_uint(Ash[base + (gid + 8) * 36 + tig]);
                afh[mt][2] = __float_as_uint(Ash[base + gid * 36 + tig + 4]);
                afh[mt][3] = __float_as_uint(Ash[base + (gid + 8) * 36 + tig + 4]);
                afl[mt][0] = __float_as_uint(Asl[base + gid * 36 + tig]);
                afl[mt][1] = __float_as_uint(Asl[base + (gid + 8) * 36 + tig]);
                afl[mt][2] = __float_as_uint(Asl[base + gid * 36 + tig + 4]);
                afl[mt][3] = __float_as_uint(Asl[base + (gid + 8) * 36 + tig + 4]);
            }
#pragma unroll
            for (int nt = 0; nt < 12; nt++) {
                const int col = w * 96 + nt * 8 + gid;
                const float* bp = wo + (size_t)col * EMB + kt * 32 + ks * 8;
                unsigned bh[2];
                bh[0] = f2tf(bp[tig]);
                bh[1] = f2tf(bp[tig + 4]);
#pragma unroll
                for (int mt = 0; mt < 2; mt++) {
                    mma8(acc[mt][nt], afh[mt], bh);
                    mma8(acc[mt][nt], afl[mt], bh);
                }
            }
        }
    }

    __syncthreads();   // all in-place reads complete before any write

#pragma unroll
    for (int mt = 0; mt < 2; mt++) {
#pragma unroll
        for (int nt = 0; nt < 12; nt++) {
            const int row = strip + mt * 16 + gid;
            const int col = w * 96 + nt * 8 + 2 * tig;
            const float b0 = bo[col], b1 = bo[col + 1];
            *(float2*)(io + (size_t)row * EMB + col) =
                make_float2(acc[mt][nt][0] + b0, acc[mt][nt][1] + b1);
            *(float2*)(io + (size_t)(row + 8) * EMB + col) =
                make_float2(acc[mt][nt][2] + b0, acc[mt][nt][3] + b1);
        }
    }
}

extern "C" void kernel_launch(void* const* d_in, const int* in_sizes, int n_in,
                              void* d_out, int out_size)
{
    const float* x  = (const float*)d_in[0];
    const float* wq = (const float*)d_in[1];
    const float* bq = (const float*)d_in[2];
    const float* wk = (const float*)d_in[3];
    const float* bk = (const float*)d_in[4];
    const float* wv = (const float*)d_in[5];
    const float* bv = (const float*)d_in[6];
    const float* wo = (const float*)d_in[7];
    const float* bo = (const float*)d_in[8];
    float* out = (float*)d_out;

    cudaFuncSetAttribute(qkv_gemm_kernel, cudaFuncAttributeMaxDynamicSharedMemorySize, GEMM_SMEM);
    cudaFuncSetAttribute(flash_kernel, cudaFuncAttributeMaxDynamicSharedMemorySize, FLASH_SMEM);

    for (int g = 0; g < 4; g++) {
        dim3 ggrid(18, 16);
        qkv_gemm_kernel<<<ggrid, 256, GEMM_SMEM>>>(x, wq, bq, wk, bk, wv, bv, g);
        dim3 fgrid(16, NHEADS, 2);
        flash_kernel<<<fgrid, 128, FLASH_SMEM>>>(out, g);
    }
    outproj_kernel<<<MTOT / 32, 256>>>(out, wo, bo);
}

// round 9
// speedup vs baseline: 1.5742x; 1.0974x over previous
#include <cuda_runtime.h>
#include <cstdint>
#include <cstdlib>

#define BATCH   8
#define NSEQ    1024
#define EMB     768
#define NHEADS  12
#define HDIM    64
#define MTOT    (BATCH * NSEQ)
#define HSTRIDE (NSEQ * HDIM)     // 65536

// Scratch: Q,K,V for TWO batches. 18.9 MiB. [lb(2)][sel(3)][head][n][d]
__device__ float g_s[2 * 3 * NHEADS * NSEQ * HDIM];

namespace {
struct EagerLoad { EagerLoad() { setenv("CUDA_MODULE_LOADING", "EAGER", 1); } };
EagerLoad eager_load_instance_;
}

// ---------------------------------------------------------------------------
// tf32 helpers
// ---------------------------------------------------------------------------
__device__ __forceinline__ unsigned f2tf(float x) {
    unsigned r;
    asm("cvt.rna.tf32.f32 %0, %1;" : "=r"(r) : "f"(x));
    return r;
}
__device__ __forceinline__ float f2tff(float x) { return __uint_as_float(f2tf(x)); }

__device__ __forceinline__ void mma8(float* c, const unsigned* a, const unsigned* b) {
    asm volatile(
        "mma.sync.aligned.m16n8k8.row.col.f32.tf32.tf32.f32 "
        "{%0,%1,%2,%3}, {%4,%5,%6,%7}, {%8,%9}, {%0,%1,%2,%3};\n"
        : "+f"(c[0]), "+f"(c[1]), "+f"(c[2]), "+f"(c[3])
        : "r"(a[0]), "r"(a[1]), "r"(a[2]), "r"(a[3]), "r"(b[0]), "r"(b[1]));
}

__device__ __forceinline__ float4 hi4(float4 v) {
    return make_float4(f2tff(v.x), f2tff(v.y), f2tff(v.z), f2tff(v.w));
}
__device__ __forceinline__ float4 lo4(float4 v, float4 h) {
    return make_float4(f2tff(v.x - h.x), f2tff(v.y - h.y),
                       f2tff(v.z - h.z), f2tff(v.w - h.w));
}

// ---------------------------------------------------------------------------
// Fused QKV GEMM (tf32x2: x hi+lo at fragment load, W hi only) for TWO
// batches. Grid (18, 16). Double-buffered smem: A raw fp32, B tf32-hi.
// ---------------------------------------------------------------------------
#define GEMM_SMEM (4 * 128 * 36 * 4)   // Araw[2] + Bh[2] = 73728 B

__global__ __launch_bounds__(256) void qkv_gemm_kernel(
    const float* __restrict__ x,
    const float* __restrict__ wq, const float* __restrict__ bq,
    const float* __restrict__ wk, const float* __restrict__ bk,
    const float* __restrict__ wv, const float* __restrict__ bv,
    int group)
{
    extern __shared__ float sm[];
    float* Ar = sm;                    // [2][128*36] raw fp32
    float* Bh = sm + 2 * 128 * 36;     // [2][128*36] tf32-hi

    const int bx = blockIdx.x;         // 0..17
    const int by = blockIdx.y;         // 0..15
    const int sel = bx / 6;
    const int bxx = bx % 6;
    const float* W    = (sel == 0) ? wq : (sel == 1) ? wk : wv;
    const float* bias = (sel == 0) ? bq : (sel == 1) ? bk : bv;
    const float* A = x + (size_t)(group * 2 * NSEQ) * EMB;

    const int tid = threadIdx.x;
    const int lane = tid & 31;
    const int w = tid >> 5;
    const int wm = w & 3;
    const int wn = w >> 2;
    const int gid = lane >> 2;
    const int tig = lane & 3;

    const int lrow = tid >> 1;
    const int lcol = (tid & 1) * 16;

    const float* Ag = A + (size_t)(by * 128 + lrow) * EMB + lcol;
    const float* Wg = W + (size_t)(bxx * 128 + lrow) * EMB + lcol;

    float acc[2][8][4];
#pragma unroll
    for (int mt = 0; mt < 2; mt++)
#pragma unroll
        for (int nt = 0; nt < 8; nt++)
#pragma unroll
            for (int i = 0; i < 4; i++) acc[mt][nt][i] = 0.f;

    float4 ra[4], rb[4];
#pragma unroll
    for (int j = 0; j < 4; j++) {
        ra[j] = *(const float4*)(Ag + j * 4);
        rb[j] = *(const float4*)(Wg + j * 4);
    }
#pragma unroll
    for (int j = 0; j < 4; j++) {
        *(float4*)(Ar + lrow * 36 + lcol + j * 4) = ra[j];
        *(float4*)(Bh + lrow * 36 + lcol + j * 4) = hi4(rb[j]);
    }
    __syncthreads();

    const int NKT = EMB / 32;   // 24
    for (int kt = 0; kt < NKT; kt++) {
        const int cur = kt & 1;
        if (kt + 1 < NKT) {
#pragma unroll
            for (int j = 0; j < 4; j++) {
                ra[j] = *(const float4*)(Ag + (kt + 1) * 32 + j * 4);
                rb[j] = *(const float4*)(Wg + (kt + 1) * 32 + j * 4);
            }
        }
        const float* Ab = Ar + cur * 128 * 36;
        const float* Bb = Bh + cur * 128 * 36;
#pragma unroll
        for (int ks = 0; ks < 4; ks++) {
            unsigned afh[2][4], afl[2][4], bfh[8][2];
#pragma unroll
            for (int mt = 0; mt < 2; mt++) {
                const int base = (wm * 32 + mt * 16) * 36 + ks * 8;
                float a0 = Ab[base + gid * 36 + tig];
                float a1 = Ab[base + (gid + 8) * 36 + tig];
                float a2 = Ab[base + gid * 36 + tig + 4];
                float a3 = Ab[base + (gid + 8) * 36 + tig + 4];
                float h0 = f2tff(a0), h1 = f2tff(a1), h2 = f2tff(a2), h3 = f2tff(a3);
                afh[mt][0] = __float_as_uint(h0); afl[mt][0] = f2tf(a0 - h0);
                afh[mt][1] = __float_as_uint(h1); afl[mt][1] = f2tf(a1 - h1);
                afh[mt][2] = __float_as_uint(h2); afl[mt][2] = f2tf(a2 - h2);
                afh[mt][3] = __float_as_uint(h3); afl[mt][3] = f2tf(a3 - h3);
            }
#pragma unroll
            for (int nt = 0; nt < 8; nt++) {
                const int base = (wn * 64 + nt * 8 + gid) * 36 + ks * 8;
                bfh[nt][0] = __float_as_uint(Bb[base + tig]);
                bfh[nt][1] = __float_as_uint(Bb[base + tig + 4]);
            }
#pragma unroll
            for (int mt = 0; mt < 2; mt++)
#pragma unroll
                for (int nt = 0; nt < 8; nt++) {
                    mma8(acc[mt][nt], afh[mt], bfh[nt]);
                    mma8(acc[mt][nt], afl[mt], bfh[nt]);
                }
        }
        if (kt + 1 < NKT) {
            const int nxt = cur ^ 1;
#pragma unroll
            for (int j = 0; j < 4; j++) {
                *(float4*)(Ar + nxt * 128 * 36 + lrow * 36 + lcol + j * 4) = ra[j];
                *(float4*)(Bh + nxt * 128 * 36 + lrow * 36 + lcol + j * 4) = hi4(rb[j]);
            }
            __syncthreads();
        }
    }

#pragma unroll
    for (int mt = 0; mt < 2; mt++) {
        const int grow = by * 128 + wm * 32 + mt * 16 + gid;   // 0..2047
        const int lb = grow >> 10;
        const int n = grow & 1023;
#pragma unroll
        for (int nt = 0; nt < 8; nt++) {
            const int wcol = bxx * 128 + wn * 64 + nt * 8 + 2 * tig;
            const float b0 = bias[wcol], b1 = bias[wcol + 1];
            const int h_ = wcol >> 6, d_ = wcol & 63;
            float* dst = g_s +
                (((size_t)(lb * 3 + sel) * NHEADS + h_) * NSEQ + n) * HDIM + d_;
            *(float2*)dst = make_float2(acc[mt][nt][0] + b0, acc[mt][nt][1] + b1);
            *(float2*)(dst + 8 * HDIM) =
                make_float2(acc[mt][nt][2] + b0, acc[mt][nt][3] + b1);
        }
    }
}

// ---------------------------------------------------------------------------
// Flash attention: S = QK^T tf32x3 with K hi/lo PRECOMPUTED in smem at tile
// load (shared transform done once, not per consuming warp); P*V single tf32.
// Grid (16, 12, 2); 128 threads; 3 CTAs/SM target (regs<=170, smem 70656).
// ---------------------------------------------------------------------------
#define KPITCH 68
#define VPITCH 72
#define PPITCH 68
#define FLASH_SMEM ((2 * 64 * KPITCH + 64 * VPITCH + 4 * 16 * PPITCH) * 4)  // 70656

__global__ __launch_bounds__(128, 3) void flash_kernel(float* __restrict__ out, int group)
{
    extern __shared__ float sm[];
    float* ksh = sm;                         // [64][68] K hi
    float* ksl = ksh + 64 * KPITCH;          // [64][68] K lo
    float* vsh = ksl + 64 * KPITCH;          // [64][72] V hi
    float* psh = vsh + 64 * VPITCH;          // [4][16][68] P

    const int h = blockIdx.y;
    const int lb = blockIdx.z;
    const int q0 = blockIdx.x * 64;
    const int tid = threadIdx.x;
    const int lane = tid & 31;
    const int w = tid >> 5;                  // 0..3
    const int gid = lane >> 2;
    const int tig = lane & 3;
    float* pw = psh + w * 16 * PPITCH;

    const float* qg = g_s + ((size_t)(lb * 3 + 0) * NHEADS + h) * HSTRIDE;
    const float* kg = g_s + ((size_t)(lb * 3 + 1) * NHEADS + h) * HSTRIDE;
    const float* vg = g_s + ((size_t)(lb * 3 + 2) * NHEADS + h) * HSTRIDE;

    const int r0 = q0 + w * 16 + gid;

    // Q fragments hi/lo in registers (reused across all 16 key tiles)
    unsigned qah[8][4], qal[8][4];
#pragma unroll
    for (int kk = 0; kk < 8; kk++) {
        const int c = kk * 8 + tig;
        float v0 = qg[(size_t)r0 * HDIM + c];
        float v1 = qg[(size_t)(r0 + 8) * HDIM + c];
        float v2 = qg[(size_t)r0 * HDIM + c + 4];
        float v3 = qg[(size_t)(r0 + 8) * HDIM + c + 4];
        float h0 = f2tff(v0), h1 = f2tff(v1), h2 = f2tff(v2), h3 = f2tff(v3);
        qah[kk][0] = __float_as_uint(h0); qal[kk][0] = f2tf(v0 - h0);
        qah[kk][1] = __float_as_uint(h1); qal[kk][1] = f2tf(v1 - h1);
        qah[kk][2] = __float_as_uint(h2); qal[kk][2] = f2tf(v2 - h2);
        qah[kk][3] = __float_as_uint(h3); qal[kk][3] = f2tf(v3 - h3);
    }

    float o[8][4];
#pragma unroll
    for (int dt = 0; dt < 8; dt++)
#pragma unroll
        for (int i = 0; i < 4; i++) o[dt][i] = 0.f;
    float m0 = -1e30f, m1 = -1e30f, l0 = 0.f, l1 = 0.f;

    for (int kt = 0; kt < 16; kt++) {
        __syncthreads();
        // Tile load: K hi/lo (split ONCE here), V hi
#pragma unroll
        for (int i = 0; i < 8; i++) {
            const int idx = i * 128 + tid;          // 0..1023
            const int row = idx >> 4;
            const int c4 = (idx & 15) * 4;
            float4 kv = *(const float4*)(kg + (size_t)(kt * 64 + row) * HDIM + c4);
            float4 hh = hi4(kv);
            *(float4*)(ksh + row * KPITCH + c4) = hh;
            *(float4*)(ksl + row * KPITCH + c4) = lo4(kv, hh);
            float4 vv = *(const float4*)(vg + (size_t)(kt * 64 + row) * HDIM + c4);
            *(float4*)(vsh + row * VPITCH + c4) = hi4(vv);
        }
        __syncthreads();

        // S = Q K^T (tf32x3)
        float s[8][4];
#pragma unroll
        for (int nt = 0; nt < 8; nt++)
#pragma unroll
            for (int i = 0; i < 4; i++) s[nt][i] = 0.f;
#pragma unroll
        for (int kk = 0; kk < 8; kk++) {
#pragma unroll
            for (int nt = 0; nt < 8; nt++) {
                const int base = (nt * 8 + gid) * KPITCH + kk * 8;
                unsigned bh[2], bl[2];
                bh[0] = __float_as_uint(ksh[base + tig]);
                bh[1] = __float_as_uint(ksh[base + tig + 4]);
                bl[0] = __float_as_uint(ksl[base + tig]);
                bl[1] = __float_as_uint(ksl[base + tig + 4]);
                mma8(s[nt], qah[kk], bh);
                mma8(s[nt], qah[kk], bl);
                mma8(s[nt], qal[kk], bh);
            }
        }

        // Online softmax
        float mx0 = -1e30f, mx1 = -1e30f;
#pragma unroll
        for (int nt = 0; nt < 8; nt++) {
            mx0 = fmaxf(mx0, fmaxf(s[nt][0], s[nt][1]));
            mx1 = fmaxf(mx1, fmaxf(s[nt][2], s[nt][3]));
        }
        mx0 = fmaxf(mx0, __shfl_xor_sync(0xffffffffu, mx0, 1));
        mx0 = fmaxf(mx0, __shfl_xor_sync(0xffffffffu, mx0, 2));
        mx1 = fmaxf(mx1, __shfl_xor_sync(0xffffffffu, mx1, 1));
        mx1 = fmaxf(mx1, __shfl_xor_sync(0xffffffffu, mx1, 2));
        const float nm0 = fmaxf(m0, mx0), nm1 = fmaxf(m1, mx1);
        const float sc0 = __expf(m0 - nm0), sc1 = __expf(m1 - nm1);
        float rs0 = 0.f, rs1 = 0.f;
#pragma unroll
        for (int nt = 0; nt < 8; nt++) {
            s[nt][0] = __expf(s[nt][0] - nm0); rs0 += s[nt][0];
            s[nt][1] = __expf(s[nt][1] - nm0); rs0 += s[nt][1];
            s[nt][2] = __expf(s[nt][2] - nm1); rs1 += s[nt][2];
            s[nt][3] = __expf(s[nt][3] - nm1); rs1 += s[nt][3];
        }
        rs0 += __shfl_xor_sync(0xffffffffu, rs0, 1);
        rs0 += __shfl_xor_sync(0xffffffffu, rs0, 2);
        rs1 += __shfl_xor_sync(0xffffffffu, rs1, 1);
        rs1 += __shfl_xor_sync(0xffffffffu, rs1, 2);
        l0 = l0 * sc0 + rs0;
        l1 = l1 * sc1 + rs1;
#pragma unroll
        for (int dt = 0; dt < 8; dt++) {
            o[dt][0] *= sc0; o[dt][1] *= sc0;
            o[dt][2] *= sc1; o[dt][3] *= sc1;
        }
        m0 = nm0; m1 = nm1;

        // P -> per-warp smem (single tf32), re-fragment as A for P*V
#pragma unroll
        for (int nt = 0; nt < 8; nt++) {
            const int c0 = nt * 8 + 2 * tig;
            pw[gid * PPITCH + c0]           = f2tff(s[nt][0]);
            pw[gid * PPITCH + c0 + 1]       = f2tff(s[nt][1]);
            pw[(gid + 8) * PPITCH + c0]     = f2tff(s[nt][2]);
            pw[(gid + 8) * PPITCH + c0 + 1] = f2tff(s[nt][3]);
        }
        __syncwarp();

#pragma unroll
        for (int ks2 = 0; ks2 < 8; ks2++) {
            unsigned pa[4];
            pa[0] = __float_as_uint(pw[gid * PPITCH + ks2 * 8 + tig]);
            pa[1] = __float_as_uint(pw[(gid + 8) * PPITCH + ks2 * 8 + tig]);
            pa[2] = __float_as_uint(pw[gid * PPITCH + ks2 * 8 + tig + 4]);
            pa[3] = __float_as_uint(pw[(gid + 8) * PPITCH + ks2 * 8 + tig + 4]);
#pragma unroll
            for (int dt = 0; dt < 8; dt++) {
                unsigned bb[2];
                bb[0] = __float_as_uint(vsh[(ks2 * 8 + tig) * VPITCH + dt * 8 + gid]);
                bb[1] = __float_as_uint(vsh[(ks2 * 8 + tig + 4) * VPITCH + dt * 8 + gid]);
                mma8(o[dt], pa, bb);
            }
        }
    }

    const float inv0 = 1.f / l0, inv1 = 1.f / l1;
    const size_t base0 =
        ((size_t)((group * 2 + lb) * NSEQ + r0)) * EMB + h * HDIM;
#pragma unroll
    for (int dt = 0; dt < 8; dt++) {
        const int d = dt * 8 + 2 * tig;
        *(float2*)(out + base0 + d) = make_float2(o[dt][0] * inv0, o[dt][1] * inv0);
        *(float2*)(out + base0 + (size_t)8 * EMB + d) =
            make_float2(o[dt][2] * inv1, o[dt][3] * inv1);
    }
}

// ---------------------------------------------------------------------------
// In-place output projection (tf32x2: ctx split hi/lo, Wo single tf32).
// ---------------------------------------------------------------------------
__global__ __launch_bounds__(256) void outproj_kernel(
    float* __restrict__ io, const float* __restrict__ wo, const float* __restrict__ bo)
{
    __shared__ float Ash[32 * 36];
    __shared__ float Asl[32 * 36];

    const int tid = threadIdx.x;
    const int lane = tid & 31;
    const int w = tid >> 5;
    const int gid = lane >> 2;
    const int tig = lane & 3;
    const int strip = blockIdx.x * 32;

    const int arow = tid >> 3;
    const int acol = (tid & 7) * 4;
    const float* Ag = io + (size_t)(strip + arow) * EMB + acol;

    float acc[2][12][4];
#pragma unroll
    for (int mt = 0; mt < 2; mt++)
#pragma unroll
        for (int nt = 0; nt < 12; nt++)
#pragma unroll
            for (int i = 0; i < 4; i++) acc[mt][nt][i] = 0.f;

    float4 va = *(const float4*)(Ag);

    for (int kt = 0; kt < 24; kt++) {
        __syncthreads();
        {
            float4 hh = hi4(va);
            *(float4*)(Ash + arow * 36 + acol) = hh;
            *(float4*)(Asl + arow * 36 + acol) = lo4(va, hh);
        }
        __syncthreads();
        if (kt + 1 < 24) va = *(const float4*)(Ag + (kt + 1) * 32);

#pragma unroll
        for (int ks = 0; ks < 4; ks++) {
            unsigned afh[2][4], afl[2][4];
#pragma unroll
            for (int mt = 0; mt < 2; mt++) {
                const int base = (mt * 16) * 36 + ks * 8;
                afh[mt][0] = __float_as_uint(Ash[base + gid * 36 + tig]);
                afh[mt][1] = __float_as_uint(Ash[base + (gid + 8) * 36 + tig]);
                afh[mt][2] = __float_as_uint(Ash[base + gid * 36 + tig + 4]);
                afh[mt][3] = __float_as_uint(Ash[base + (gid + 8) * 36 + tig + 4]);
                afl[mt][0] = __float_as_uint(Asl[base + gid * 36 + tig]);
                afl[mt][1] = __float_as_uint(Asl[base + (gid + 8) * 36 + tig]);
                afl[mt][2] = __float_as_uint(Asl[base + gid * 36 + tig + 4]);
                afl[mt][3] = __float_as_uint(Asl[base + (gid + 8) * 36 + tig + 4]);
            }
#pragma unroll
            for (int nt = 0; nt < 12; nt++) {
                const int col = w * 96 + nt * 8 + gid;
                const float* bp = wo + (size_t)col * EMB + kt * 32 + ks * 8;
                unsigned bh[2];
                bh[0] = f2tf(bp[tig]);
                bh[1] = f2tf(bp[tig + 4]);
#pragma unroll
                for (int mt = 0; mt < 2; mt++) {
                    mma8(acc[mt][nt], afh[mt], bh);
                    mma8(acc[mt][nt], afl[mt], bh);
                }
            }
        }
    }

    __syncthreads();   // all in-place reads complete before any write

#pragma unroll
    for (int mt = 0; mt < 2; mt++) {
#pragma unroll
        for (int nt = 0; nt < 12; nt++) {
            const int row = strip + mt * 16 + gid;
            const int col = w * 96 + nt * 8 + 2 * tig;
            const float b0 = bo[col], b1 = bo[col + 1];
            *(float2*)(io + (size_t)row * EMB + col) =
                make_float2(acc[mt][nt][0] + b0, acc[mt][nt][1] + b1);
            *(float2*)(io + (size_t)(row + 8) * EMB + col) =
                make_float2(acc[mt][nt][2] + b0, acc[mt][nt][3] + b1);
        }
    }
}

extern "C" void kernel_launch(void* const* d_in, const int* in_sizes, int n_in,
                              void* d_out, int out_size)
{
    const float* x  = (const float*)d_in[0];
    const float* wq = (const float*)d_in[1];
    const float* bq = (const float*)d_in[2];
    const float* wk = (const float*)d_in[3];
    const float* bk = (const float*)d_in[4];
    const float* wv = (const float*)d_in[5];
    const float* bv = (const float*)d_in[6];
    const float* wo = (const float*)d_in[7];
    const float* bo = (const float*)d_in[8];
    float* out = (float*)d_out;

    cudaFuncSetAttribute(qkv_gemm_kernel, cudaFuncAttributeMaxDynamicSharedMemorySize, GEMM_SMEM);
    cudaFuncSetAttribute(flash_kernel, cudaFuncAttributeMaxDynamicSharedMemorySize, FLASH_SMEM);
    cudaFuncSetAttribute(flash_kernel, cudaFuncAttributePreferredSharedMemoryCarveout, 100);

    for (int g = 0; g < 4; g++) {
        dim3 ggrid(18, 16);
        qkv_gemm_kernel<<<ggrid, 256, GEMM_SMEM>>>(x, wq, bq, wk, bk, wv, bv, g);
        dim3 fgrid(16, NHEADS, 2);
        flash_kernel<<<fgrid, 128, FLASH_SMEM>>>(out, g);
    }
    outproj_kernel<<<MTOT / 32, 256>>>(out, wo, bo);
}